// round 16
// baseline (speedup 1.0000x reference)
#include <cuda_runtime.h>
#include <cuda_fp16.h>
#include <math.h>
#include <stdint.h>

#define NNODES 81920
#define NEDGES 1310720
#define NG     4096
#define NPG    20
#define IND    128
#define D      256
#define HIDC   64
#define NH     4

// ---------------- scratch (no allocations allowed) ----------------
__device__ __align__(16) float g_h1lin[NNODES * D];
__device__ __align__(16) __half g_xhi[NNODES * IND];
__device__ __align__(16) __half g_w1h[D * IND];
__device__ __align__(16) float g_W2T[D * D];       // W2T[k*256+c] = W2[c][k]
__device__ __align__(16) float g_WhT[D * HIDC];    // WhT[k*64+j]  = Wh[j][k]
__device__ __align__(16) float g_v[8 * D];         // layer-2 score vectors (W2^T a2)
__device__ __align__(16) float g_u1[8 * IND];      // layer-1 score vectors (W1^T a1)
__device__ __align__(16) float g_s1[NNODES * 8];   // per-node layer-1 scores (4 src, 4 dst)
__device__ __align__(16) float g_Y[NG * NH * D];   // per-graph per-head aggregated vectors
__device__ int g_hist[NG * NPG * NPG];             // [g][dst][src]; k_tail re-zeroes

// ================= helpers =================
__device__ __forceinline__ uint32_t cvta_smem(const void* p) {
    uint32_t a;
    asm("{ .reg .u64 t; cvta.to.shared.u64 t, %1; cvt.u32.u64 %0, t; }" : "=r"(a) : "l"(p));
    return a;
}
__device__ __forceinline__ void cp16(uint32_t dst, const void* src) {
    asm volatile("cp.async.cg.shared.global [%0], [%1], 16;" :: "r"(dst), "l"(src) : "memory");
}
__device__ __forceinline__ void mma_f16(float* d, const uint32_t* a, uint32_t b0, uint32_t b1) {
    asm volatile(
        "mma.sync.aligned.m16n8k16.row.col.f32.f16.f16.f32 "
        "{%0,%1,%2,%3}, {%4,%5,%6,%7}, {%8,%9}, {%0,%1,%2,%3};"
        : "+f"(d[0]), "+f"(d[1]), "+f"(d[2]), "+f"(d[3])
        : "r"(a[0]), "r"(a[1]), "r"(a[2]), "r"(a[3]), "r"(b0), "r"(b1));
}
#define LDSM4(r0, r1, r2, r3, addr) \
    asm volatile("ldmatrix.sync.aligned.m8n8.x4.shared.b16 {%0,%1,%2,%3}, [%4];" \
                 : "=r"(r0), "=r"(r1), "=r"(r2), "=r"(r3) : "r"(addr))
__device__ __forceinline__ float lrelu(float v) { return (v >= 0.f) ? v : 0.2f * v; }
__device__ __forceinline__ float eluf(float v) { return (v > 0.f) ? v : (__expf(v) - 1.f); }

// ---------------- edge histogram ----------------
__global__ void k_hist(const int* __restrict__ ei) {
    int e = blockIdx.x * blockDim.x + threadIdx.x;
    if (e < NEDGES) {
        int s = ei[e];
        int d = ei[NEDGES + e];
        int g = d / NPG;
        atomicAdd(&g_hist[g * 400 + (d - g * NPG) * NPG + (s - g * NPG)], 1);
    }
}

// ---------------- prep: x->fp16, W1->fp16, W2T, WhT, v = W2^T a2, u1 = W1^T a1 ----------------
#define N4X  (NNODES * IND / 4)
#define N4W1 (D * IND / 4)
#define NW2T (D * D)
#define NWHT (D * HIDC)
#define NV   (8 * D)
#define NU1  (8 * IND)
#define PREP_TOTAL (N4X + N4W1 + NW2T + NWHT + NV + NU1)
__global__ void k_prep(const float* __restrict__ x, const float* __restrict__ W1,
                       const float* __restrict__ W2, const float* __restrict__ a1s,
                       const float* __restrict__ a1d, const float* __restrict__ a2s,
                       const float* __restrict__ a2d, const float* __restrict__ Wh) {
    int i = blockIdx.x * blockDim.x + threadIdx.x;
    if (i < N4X) {
        float4 v = ((const float4*)x)[i];
        __half h[4] = {__float2half(v.x), __float2half(v.y),
                       __float2half(v.z), __float2half(v.w)};
        ((uint2*)g_xhi)[i] = *(uint2*)h;
    } else if (i < N4X + N4W1) {
        int j = i - N4X;
        float4 v = ((const float4*)W1)[j];
        __half h[4] = {__float2half(v.x), __float2half(v.y),
                       __float2half(v.z), __float2half(v.w)};
        ((uint2*)g_w1h)[j] = *(uint2*)h;
    } else if (i < N4X + N4W1 + NW2T) {
        int j = i - (N4X + N4W1);          // j = k*256 + c
        int k = j >> 8, c = j & 255;
        g_W2T[j] = W2[c * D + k];
    } else if (i < N4X + N4W1 + NW2T + NWHT) {
        int j = i - (N4X + N4W1 + NW2T);   // j = k*64 + jc
        int k = j >> 6, jc = j & 63;
        g_WhT[j] = Wh[jc * D + k];
    } else if (i < N4X + N4W1 + NW2T + NWHT + NV) {
        int j = i - (N4X + N4W1 + NW2T + NWHT);   // j = vec*256 + k
        int vec = j >> 8, k = j & 255;
        int h = vec & 3;
        const float* av = ((vec < 4) ? a2s : a2d) + h * HIDC;
        float acc = 0.f;
        #pragma unroll 8
        for (int jj = 0; jj < HIDC; jj++)
            acc += av[jj] * W2[(h * HIDC + jj) * D + k];
        g_v[j] = acc;
    } else if (i < PREP_TOTAL) {
        int j = i - (N4X + N4W1 + NW2T + NWHT + NV);  // j = vec*128 + k
        int vec = j >> 7, k = j & 127;
        int h = vec & 3;
        const float* av = ((vec < 4) ? a1s : a1d) + h * HIDC;
        float acc = 0.f;
        #pragma unroll 8
        for (int jj = 0; jj < HIDC; jj++)
            acc += av[jj] * W1[(h * HIDC + jj) * IND + k];
        g_u1[j] = acc;
    }
}

// ---------------- per-node layer-1 scores: s1[i][vec] = x[i] . u1[vec] ----------------
__global__ __launch_bounds__(256)
void k_score(const float* __restrict__ x) {
    __shared__ float xs_sh[32][132];
    __shared__ float u1sh[8][132];
    const int tid = threadIdx.x;
    const int n0 = blockIdx.x * 32;

    for (int i = tid; i < 32 * IND; i += 256)
        xs_sh[i >> 7][i & 127] = x[(size_t)n0 * IND + i];
    for (int i = tid; i < 8 * IND; i += 256)
        u1sh[i >> 7][i & 127] = g_u1[i];
    __syncthreads();

    const int n = tid >> 3, v = tid & 7;
    float a0 = 0.f, a1 = 0.f, a2 = 0.f, a3 = 0.f;
    #pragma unroll
    for (int k = 0; k < IND; k += 4) {
        a0 += xs_sh[n][k]     * u1sh[v][k];
        a1 += xs_sh[n][k + 1] * u1sh[v][k + 1];
        a2 += xs_sh[n][k + 2] * u1sh[v][k + 2];
        a3 += xs_sh[n][k + 3] * u1sh[v][k + 3];
    }
    g_s1[(size_t)(n0 + n) * 8 + v] = (a0 + a1) + (a2 + a3);
}

// ============ fp16 mma.sync GEMM: C[M,256] = A[M,K] * Bh[256,K]^T (single-A) ============
#define ROWB 80
#define HALF_TILE (128 * ROWB)
#define STAGE_BYTES (3 * HALF_TILE)
#define GEMM_SMEM 69632

template <int K>
__global__ __launch_bounds__(256, 2)
void k_gemm_mma(const __half* __restrict__ Ahi, const __half* __restrict__ Bh,
                float* __restrict__ C) {
    extern __shared__ __align__(128) char smem[];
    const int tid = threadIdx.x;
    const int lane = tid & 31, wid = tid >> 5;
    const int warpm = wid & 3, warpn = wid >> 2;
    const int m0 = blockIdx.x * 128, n0 = blockIdx.y * 128;
    const uint32_t sb = cvta_smem(smem);
    const int NSTAGE = K / 32;

    const int arow = lane & 15, akh = lane >> 4;
    const int brow = ((lane >> 4) << 3) | (lane & 7);
    const int bkh = (lane >> 3) & 1;

    float acc[2][8][4];
    #pragma unroll
    for (int i = 0; i < 2; i++)
        #pragma unroll
        for (int j = 0; j < 8; j++)
            #pragma unroll
            for (int q = 0; q < 4; q++) acc[i][j][q] = 0.f;

    auto prefetch = [&](int s) {
        uint32_t base = sb + (uint32_t)(s & 1) * STAGE_BYTES;
        #pragma unroll
        for (int l = 0; l < 2; l++) {
            int u = tid + l * 256;
            int row = u >> 2, ku = u & 3;
            uint32_t doff = (uint32_t)(row * ROWB + ku * 16);
            size_t goA = (size_t)(m0 + row) * K + s * 32 + ku * 8;
            size_t goB = (size_t)(n0 + row) * K + s * 32 + ku * 8;
            cp16(base + doff, Ahi + goA);
            cp16(base + 2 * HALF_TILE + doff, Bh + goB);
        }
        asm volatile("cp.async.commit_group;" ::: "memory");
    };

    prefetch(0);
    #pragma unroll 1
    for (int s = 0; s < NSTAGE; s++) {
        if (s + 1 < NSTAGE) {
            prefetch(s + 1);
            asm volatile("cp.async.wait_group 1;" ::: "memory");
        } else {
            asm volatile("cp.async.wait_group 0;" ::: "memory");
        }
        __syncthreads();

        const uint32_t sbase = sb + (uint32_t)(s & 1) * STAGE_BYTES;
        const uint32_t sAhi = sbase;
        const uint32_t sB   = sbase + 2 * HALF_TILE;

        #pragma unroll
        for (int ks = 0; ks < 2; ks++) {
            const uint32_t koff = (uint32_t)(ks * 32);
            uint32_t ahi[2][4], bf[4][4];

            uint32_t aA = sAhi + (uint32_t)((warpm * 32 + arow) * ROWB) + koff + akh * 16;
            LDSM4(ahi[0][0], ahi[0][1], ahi[0][2], ahi[0][3], aA);
            LDSM4(ahi[1][0], ahi[1][1], ahi[1][2], ahi[1][3], aA + 16 * ROWB);

            uint32_t aB = sB + (uint32_t)((warpn * 64 + brow) * ROWB) + koff + bkh * 16;
            #pragma unroll
            for (int jp = 0; jp < 4; jp++)
                LDSM4(bf[jp][0], bf[jp][1], bf[jp][2], bf[jp][3], aB + jp * 16 * ROWB);

            #pragma unroll
            for (int j = 0; j < 8; j++) {
                uint32_t b0 = bf[j >> 1][(j & 1) * 2];
                uint32_t b1 = bf[j >> 1][(j & 1) * 2 + 1];
                #pragma unroll
                for (int i = 0; i < 2; i++)
                    mma_f16(acc[i][j], ahi[i], b0, b1);
            }
        }
        __syncthreads();
    }

    float* stg = (float*)smem;   // [128][132]
    #pragma unroll
    for (int i = 0; i < 2; i++) {
        int r = warpm * 32 + i * 16 + (lane >> 2);
        #pragma unroll
        for (int j = 0; j < 8; j++) {
            int c = warpn * 64 + j * 8 + (lane & 3) * 2;
            stg[r * 132 + c]           = acc[i][j][0];
            stg[r * 132 + c + 1]       = acc[i][j][1];
            stg[(r + 8) * 132 + c]     = acc[i][j][2];
            stg[(r + 8) * 132 + c + 1] = acc[i][j][3];
        }
    }
    __syncthreads();
    #pragma unroll
    for (int l = 0; l < 16; l++) {
        int f = tid + l * 256;
        int row = f >> 5, c4 = f & 31;
        *(float4*)&C[(size_t)(m0 + row) * D + n0 + c4 * 4] = *(float4*)&stg[row * 132 + c4 * 4];
    }
}

// ---------------- fused attention: layer-1 GAT + layer-2 scores/agg @ node 19 ----------------
__global__ __launch_bounds__(256, 5)
void k_fused(const float* __restrict__ bias1, float* __restrict__ Y) {
    __shared__ int cnt[400];
    __shared__ __align__(16) float Wm[NH][NPG][NPG];
    __shared__ __align__(16) float ssrc[NPG][NH];
    __shared__ __align__(16) float sdst[NPG][NH];
    __shared__ float dnm[NPG][NH];
    __shared__ __align__(16) float hsh[NPG][264];
    __shared__ __align__(16) float vsh[8][260];
    __shared__ float s2[NPG][8];
    __shared__ float mx2[NH], dnm2[NH];
    __shared__ float W19w[NH][NPG];

    const int g = blockIdx.x;
    const int tid = threadIdx.x;
    const int c = tid, h = c >> 6;
    const int base = g * NPG;

    // P0: loads
    float r[NPG];
    const float* hp = g_h1lin + (size_t)base * D;
    #pragma unroll
    for (int s = 0; s < NPG; s++) r[s] = hp[s * D + c];
    const float bv = bias1[c];

    for (int i = tid; i < 400; i += 256)
        cnt[i] = g_hist[g * 400 + i] + ((i % 21) == 0 ? 1 : 0);
    for (int i = tid; i < 2048; i += 256)
        vsh[i >> 8][i & 255] = g_v[i];
    // precomputed layer-1 scores (exact, from x fp32)
    if (tid < 160) {
        int i = tid >> 3, vec = tid & 7;
        float val = g_s1[(size_t)(base + i) * 8 + vec];
        if (vec < 4) ssrc[i][vec] = val; else sdst[i][vec - 4] = val;
    }
    __syncthreads();

    // P2: dense weight matrix, all 4 heads per (d,s) cell
    for (int e = tid; e < 400; e += 256) {
        int d = e / NPG, s = e - d * NPG;
        int ct = cnt[e];
        float wx = 0.f, wy = 0.f, wz = 0.f, ww = 0.f;
        if (ct) {
            float cf = (float)ct;
            float4 sv = *(const float4*)ssrc[s];
            float4 dv = *(const float4*)sdst[d];
            wx = cf * __expf(lrelu(sv.x + dv.x));
            wy = cf * __expf(lrelu(sv.y + dv.y));
            wz = cf * __expf(lrelu(sv.z + dv.z));
            ww = cf * __expf(lrelu(sv.w + dv.w));
        }
        Wm[0][d][s] = wx; Wm[1][d][s] = wy; Wm[2][d][s] = wz; Wm[3][d][s] = ww;
    }
    __syncthreads();
    if (tid < 80) {
        int d = tid >> 2, hh = tid & 3;
        float sum = 0.f;
        #pragma unroll
        for (int s = 0; s < NPG; s++) sum += Wm[hh][d][s];
        dnm[d][hh] = 1.f / (sum + 1e-16f);
    }
    __syncthreads();

    // P3: layer-1 aggregation + bias + ELU -> hsh
    #pragma unroll
    for (int d = 0; d < NPG; d++) {
        const float4* wrow = (const float4*)Wm[h][d];
        float acc = 0.f;
        #pragma unroll
        for (int q = 0; q < 5; q++) {
            float4 wv = wrow[q];
            acc += wv.x * r[q * 4] + wv.y * r[q * 4 + 1] +
                   wv.z * r[q * 4 + 2] + wv.w * r[q * 4 + 3];
        }
        hsh[d][c] = eluf(acc * dnm[d][h] + bv);
    }
    __syncthreads();

    // P4: layer-2 scores
    if (tid < 160) {
        int i = tid >> 3, vec = tid & 7;
        const float4* hr = (const float4*)hsh[i];
        const float4* vr = (const float4*)vsh[vec];
        float a0 = 0.f, a1 = 0.f, a2 = 0.f, a3 = 0.f;
        #pragma unroll
        for (int q = 0; q < 64; q += 4) {
            float4 x0 = hr[q],     y0 = vr[q];
            float4 x1 = hr[q + 1], y1 = vr[q + 1];
            float4 x2 = hr[q + 2], y2 = vr[q + 2];
            float4 x3 = hr[q + 3], y3 = vr[q + 3];
            a0 += x0.x * y0.x + x0.y * y0.y + x0.z * y0.z + x0.w * y0.w;
            a1 += x1.x * y1.x + x1.y * y1.y + x1.z * y1.z + x1.w * y1.w;
            a2 += x2.x * y2.x + x2.y * y2.y + x2.z * y2.z + x2.w * y2.w;
            a3 += x3.x * y3.x + x3.y * y3.y + x3.z * y3.z + x3.w * y3.w;
        }
        s2[i][vec] = (a0 + a1) + (a2 + a3);
    }
    __syncthreads();

    // P5: layer-2 softmax weights at dst=19
    if (tid < NH) {
        float sd = s2[19][4 + tid];
        float m = -1e30f;
        #pragma unroll
        for (int s = 0; s < NPG; s++)
            if (cnt[380 + s]) m = fmaxf(m, lrelu(s2[s][tid] + sd));
        mx2[tid] = m;
    }
    __syncthreads();
    if (tid < 80) {
        int s = tid >> 2, hh = tid & 3;
        int ct = cnt[380 + s];
        W19w[hh][s] = ct ? (float)ct * __expf(lrelu(s2[s][hh] + s2[19][4 + hh]) - mx2[hh])
                         : 0.f;
    }
    __syncthreads();
    if (tid < NH) {
        float sum = 0.f;
        #pragma unroll
        for (int s = 0; s < NPG; s++) sum += W19w[tid][s];
        dnm2[tid] = 1.f / (sum + 1e-16f);
    }
    __syncthreads();

    // P6: Y[g][h][c]
    float y[NH] = {0.f, 0.f, 0.f, 0.f};
    #pragma unroll
    for (int s = 0; s < NPG; s++) {
        float hv = hsh[s][c];
        #pragma unroll
        for (int hh = 0; hh < NH; hh++) y[hh] += W19w[hh][s] * hv;
    }
    float* yp = Y + (size_t)g * (NH * D) + c;
    #pragma unroll
    for (int hh = 0; hh < NH; hh++) yp[hh * D] = y[hh] * dnm2[hh];
}

// ---------------- tail: 16 graphs/block; xs = Y@W2^T -> ELU -> MLP head; resets hist ----------------
#define TGP 16
#define TAIL_SMEM ((TGP * NH * D + TGP * D + D + TGP * HIDC + HIDC) * 4)
__global__ __launch_bounds__(256, 2)
void k_tail(const float* __restrict__ bias2, const float* __restrict__ bh,
            const float* __restrict__ Wc, const float* __restrict__ bc,
            float* __restrict__ out) {
    extern __shared__ float tsm[];
    float* ysh  = tsm;                                   // [TGP][NH][D]
    float* xssh = ysh + TGP * NH * D;                    // [TGP][D]
    float* b2sh = xssh + TGP * D;                        // [D]
    float* hidg = b2sh + D;                              // [TGP][HIDC]
    float* wcsh = hidg + TGP * HIDC;                     // [HIDC]

    const int tid = threadIdx.x;
    const int g0 = blockIdx.x * TGP;
    const int c = tid, h = c >> 6;

    for (int i = tid; i < TGP * NH * D; i += 256)
        ysh[i] = g_Y[(size_t)g0 * (NH * D) + i];
    b2sh[c] = bias2[c];
    if (tid < HIDC) wcsh[tid] = Wc[tid];
    for (int i = tid; i < TGP * 400; i += 256) g_hist[g0 * 400 + i] = 0;
    __syncthreads();

    // matvec: xs[g][c] = sum_k ysh[g][h][k] * W2T[k*256+c]
    float acc[TGP];
    #pragma unroll
    for (int gg = 0; gg < TGP; gg++) acc[gg] = 0.f;
    #pragma unroll 2
    for (int k = 0; k < D; k++) {
        float wv = g_W2T[k * D + c];
        #pragma unroll
        for (int gg = 0; gg < TGP; gg++)
            acc[gg] += ysh[(gg * NH + h) * D + k] * wv;
    }
    #pragma unroll
    for (int gg = 0; gg < TGP; gg++)
        xssh[gg * D + c] = eluf(acc[gg] + b2sh[c]);
    __syncthreads();

    // hidden layer: thread (j = tid&63, gp = tid>>6) handles graphs gp, gp+4, gp+8, gp+12
    {
        const int j = tid & 63, gp = tid >> 6;
        float a[4] = {0.f, 0.f, 0.f, 0.f};
        #pragma unroll 4
        for (int k = 0; k < D; k++) {
            float wv = g_WhT[k * HIDC + j];
            a[0] += xssh[gp * D + k] * wv;
            a[1] += xssh[(gp + 4) * D + k] * wv;
            a[2] += xssh[(gp + 8) * D + k] * wv;
            a[3] += xssh[(gp + 12) * D + k] * wv;
        }
        float bj = bh[j];
        #pragma unroll
        for (int q = 0; q < 4; q++) {
            float v = a[q] + bj;
            hidg[(gp + 4 * q) * HIDC + j] = (v > 0.f) ? v : 0.f;
        }
    }
    __syncthreads();

    // final reduce: warp w handles graphs w and w+8
    {
        const int lane = tid & 31, ww = tid >> 5;
        #pragma unroll
        for (int q = 0; q < 2; q++) {
            int gg = ww + q * 8;
            float s = hidg[gg * HIDC + lane] * wcsh[lane] +
                      hidg[gg * HIDC + lane + 32] * wcsh[lane + 32];
            #pragma unroll
            for (int o = 16; o; o >>= 1) s += __shfl_xor_sync(0xffffffffu, s, o);
            if (lane == 0) out[g0 + gg] = s + bc[0];
        }
    }
}

// ---------------- launcher ----------------
extern "C" void kernel_launch(void* const* d_in, const int* in_sizes, int n_in,
                              void* d_out, int out_size) {
    const float* x   = (const float*)d_in[0];
    const int*   ei  = (const int*)d_in[1];
    const float* W1  = (const float*)d_in[3];
    const float* a1s = (const float*)d_in[4];
    const float* a1d = (const float*)d_in[5];
    const float* b1  = (const float*)d_in[6];
    const float* W2  = (const float*)d_in[7];
    const float* a2s = (const float*)d_in[8];
    const float* a2d = (const float*)d_in[9];
    const float* b2  = (const float*)d_in[10];
    const float* Wh  = (const float*)d_in[11];
    const float* bh  = (const float*)d_in[12];
    const float* Wc  = (const float*)d_in[13];
    const float* bc  = (const float*)d_in[14];
    float* out = (float*)d_out;

    void *p_h1lin, *p_xhi, *p_w1h, *p_Y;
    cudaGetSymbolAddress(&p_h1lin, g_h1lin);
    cudaGetSymbolAddress(&p_xhi, g_xhi);
    cudaGetSymbolAddress(&p_w1h, g_w1h);
    cudaGetSymbolAddress(&p_Y, g_Y);

    cudaFuncSetAttribute(k_gemm_mma<IND>, cudaFuncAttributeMaxDynamicSharedMemorySize, GEMM_SMEM);
    cudaFuncSetAttribute(k_tail, cudaFuncAttributeMaxDynamicSharedMemorySize, TAIL_SMEM);

    k_hist<<<(NEDGES + 255) / 256, 256>>>(ei);                                          // idx0
    k_prep<<<(PREP_TOTAL + 255) / 256, 256>>>(x, W1, W2, a1s, a1d, a2s, a2d, Wh);       // idx1
    k_score<<<NNODES / 32, 256>>>(x);                                                   // idx2
    k_gemm_mma<IND><<<dim3(NNODES / 128, 2), 256, GEMM_SMEM>>>(                         // idx3 (profiled)
        (const __half*)p_xhi, (const __half*)p_w1h, (float*)p_h1lin);
    k_fused<<<NG, 256>>>(b1, (float*)p_Y);                                              // idx4
    k_tail<<<NG / TGP, 256, TAIL_SMEM>>>(b2, bh, Wc, bc, out);                          // idx5
}

// round 17
// speedup vs baseline: 1.1014x; 1.1014x over previous
#include <cuda_runtime.h>
#include <cuda_fp16.h>
#include <math.h>
#include <stdint.h>

#define NNODES 81920
#define NEDGES 1310720
#define NG     4096
#define NPG    20
#define IND    128
#define D      256
#define HIDC   64
#define NH     4

// ---------------- scratch (no allocations allowed) ----------------
__device__ __align__(16) float g_h1lin[NNODES * D];
__device__ __align__(16) __half g_xhi[NNODES * IND];
__device__ __align__(16) __half g_w1h[D * IND];
__device__ __align__(16) float g_W2T[D * D];
__device__ __align__(16) float g_WhT[D * HIDC];
__device__ __align__(16) float g_v[8 * D];
__device__ __align__(16) float g_u1[8 * IND];
__device__ __align__(16) float g_s1[NNODES * 8];
__device__ __align__(16) float g_Y[NG * NH * D];
__device__ int g_hist[NG * NPG * NPG];

// ================= helpers =================
__device__ __forceinline__ uint32_t cvta_smem(const void* p) {
    uint32_t a;
    asm("{ .reg .u64 t; cvta.to.shared.u64 t, %1; cvt.u32.u64 %0, t; }" : "=r"(a) : "l"(p));
    return a;
}
__device__ __forceinline__ void cp16(uint32_t dst, const void* src) {
    asm volatile("cp.async.cg.shared.global [%0], [%1], 16;" :: "r"(dst), "l"(src) : "memory");
}
__device__ __forceinline__ void mma_f16(float* d, const uint32_t* a, uint32_t b0, uint32_t b1) {
    asm volatile(
        "mma.sync.aligned.m16n8k16.row.col.f32.f16.f16.f32 "
        "{%0,%1,%2,%3}, {%4,%5,%6,%7}, {%8,%9}, {%0,%1,%2,%3};"
        : "+f"(d[0]), "+f"(d[1]), "+f"(d[2]), "+f"(d[3])
        : "r"(a[0]), "r"(a[1]), "r"(a[2]), "r"(a[3]), "r"(b0), "r"(b1));
}
#define LDSM4(r0, r1, r2, r3, addr) \
    asm volatile("ldmatrix.sync.aligned.m8n8.x4.shared.b16 {%0,%1,%2,%3}, [%4];" \
                 : "=r"(r0), "=r"(r1), "=r"(r2), "=r"(r3) : "r"(addr))
__device__ __forceinline__ float lrelu(float v) { return (v >= 0.f) ? v : 0.2f * v; }
__device__ __forceinline__ float eluf(float v) { return (v > 0.f) ? v : (__expf(v) - 1.f); }

// ---------------- edge histogram ----------------
__global__ void k_hist(const int* __restrict__ ei) {
    int e = blockIdx.x * blockDim.x + threadIdx.x;
    if (e < NEDGES) {
        int s = ei[e];
        int d = ei[NEDGES + e];
        int g = d / NPG;
        atomicAdd(&g_hist[g * 400 + (d - g * NPG) * NPG + (s - g * NPG)], 1);
    }
}

// ---------------- prep ----------------
#define N4X  (NNODES * IND / 4)
#define N4W1 (D * IND / 4)
#define NW2T (D * D)
#define NWHT (D * HIDC)
#define NV   (8 * D)
#define NU1  (8 * IND)
#define PREP_TOTAL (N4X + N4W1 + NW2T + NWHT + NV + NU1)
__global__ void k_prep(const float* __restrict__ x, const float* __restrict__ W1,
                       const float* __restrict__ W2, const float* __restrict__ a1s,
                       const float* __restrict__ a1d, const float* __restrict__ a2s,
                       const float* __restrict__ a2d, const float* __restrict__ Wh) {
    int i = blockIdx.x * blockDim.x + threadIdx.x;
    if (i < N4X) {
        float4 v = ((const float4*)x)[i];
        __half h[4] = {__float2half(v.x), __float2half(v.y),
                       __float2half(v.z), __float2half(v.w)};
        ((uint2*)g_xhi)[i] = *(uint2*)h;
    } else if (i < N4X + N4W1) {
        int j = i - N4X;
        float4 v = ((const float4*)W1)[j];
        __half h[4] = {__float2half(v.x), __float2half(v.y),
                       __float2half(v.z), __float2half(v.w)};
        ((uint2*)g_w1h)[j] = *(uint2*)h;
    } else if (i < N4X + N4W1 + NW2T) {
        int j = i - (N4X + N4W1);
        int k = j >> 8, c = j & 255;
        g_W2T[j] = W2[c * D + k];
    } else if (i < N4X + N4W1 + NW2T + NWHT) {
        int j = i - (N4X + N4W1 + NW2T);
        int k = j >> 6, jc = j & 63;
        g_WhT[j] = Wh[jc * D + k];
    } else if (i < N4X + N4W1 + NW2T + NWHT + NV) {
        int j = i - (N4X + N4W1 + NW2T + NWHT);
        int vec = j >> 8, k = j & 255;
        int h = vec & 3;
        const float* av = ((vec < 4) ? a2s : a2d) + h * HIDC;
        float acc = 0.f;
        #pragma unroll 8
        for (int jj = 0; jj < HIDC; jj++)
            acc += av[jj] * W2[(h * HIDC + jj) * D + k];
        g_v[j] = acc;
    } else if (i < PREP_TOTAL) {
        int j = i - (N4X + N4W1 + NW2T + NWHT + NV);
        int vec = j >> 7, k = j & 127;
        int h = vec & 3;
        const float* av = ((vec < 4) ? a1s : a1d) + h * HIDC;
        float acc = 0.f;
        #pragma unroll 8
        for (int jj = 0; jj < HIDC; jj++)
            acc += av[jj] * W1[(h * HIDC + jj) * IND + k];
        g_u1[j] = acc;
    }
}

// ---------------- per-node layer-1 scores ----------------
__global__ __launch_bounds__(256)
void k_score(const float* __restrict__ x) {
    __shared__ float xs_sh[32][132];
    __shared__ float u1sh[8][132];
    const int tid = threadIdx.x;
    const int n0 = blockIdx.x * 32;

    for (int i = tid; i < 32 * IND; i += 256)
        xs_sh[i >> 7][i & 127] = x[(size_t)n0 * IND + i];
    for (int i = tid; i < 8 * IND; i += 256)
        u1sh[i >> 7][i & 127] = g_u1[i];
    __syncthreads();

    const int n = tid >> 3, v = tid & 7;
    float a0 = 0.f, a1 = 0.f, a2 = 0.f, a3 = 0.f;
    #pragma unroll
    for (int k = 0; k < IND; k += 4) {
        a0 += xs_sh[n][k]     * u1sh[v][k];
        a1 += xs_sh[n][k + 1] * u1sh[v][k + 1];
        a2 += xs_sh[n][k + 2] * u1sh[v][k + 2];
        a3 += xs_sh[n][k + 3] * u1sh[v][k + 3];
    }
    g_s1[(size_t)(n0 + n) * 8 + v] = (a0 + a1) + (a2 + a3);
}

// ============ fp16 mma.sync GEMM (single-A) ============
#define ROWB 80
#define HALF_TILE (128 * ROWB)
#define STAGE_BYTES (3 * HALF_TILE)
#define GEMM_SMEM 69632

template <int K>
__global__ __launch_bounds__(256, 2)
void k_gemm_mma(const __half* __restrict__ Ahi, const __half* __restrict__ Bh,
                float* __restrict__ C) {
    extern __shared__ __align__(128) char smem[];
    const int tid = threadIdx.x;
    const int lane = tid & 31, wid = tid >> 5;
    const int warpm = wid & 3, warpn = wid >> 2;
    const int m0 = blockIdx.x * 128, n0 = blockIdx.y * 128;
    const uint32_t sb = cvta_smem(smem);
    const int NSTAGE = K / 32;

    const int arow = lane & 15, akh = lane >> 4;
    const int brow = ((lane >> 4) << 3) | (lane & 7);
    const int bkh = (lane >> 3) & 1;

    float acc[2][8][4];
    #pragma unroll
    for (int i = 0; i < 2; i++)
        #pragma unroll
        for (int j = 0; j < 8; j++)
            #pragma unroll
            for (int q = 0; q < 4; q++) acc[i][j][q] = 0.f;

    auto prefetch = [&](int s) {
        uint32_t base = sb + (uint32_t)(s & 1) * STAGE_BYTES;
        #pragma unroll
        for (int l = 0; l < 2; l++) {
            int u = tid + l * 256;
            int row = u >> 2, ku = u & 3;
            uint32_t doff = (uint32_t)(row * ROWB + ku * 16);
            size_t goA = (size_t)(m0 + row) * K + s * 32 + ku * 8;
            size_t goB = (size_t)(n0 + row) * K + s * 32 + ku * 8;
            cp16(base + doff, Ahi + goA);
            cp16(base + 2 * HALF_TILE + doff, Bh + goB);
        }
        asm volatile("cp.async.commit_group;" ::: "memory");
    };

    prefetch(0);
    #pragma unroll 1
    for (int s = 0; s < NSTAGE; s++) {
        if (s + 1 < NSTAGE) {
            prefetch(s + 1);
            asm volatile("cp.async.wait_group 1;" ::: "memory");
        } else {
            asm volatile("cp.async.wait_group 0;" ::: "memory");
        }
        __syncthreads();

        const uint32_t sbase = sb + (uint32_t)(s & 1) * STAGE_BYTES;
        const uint32_t sAhi = sbase;
        const uint32_t sB   = sbase + 2 * HALF_TILE;

        #pragma unroll
        for (int ks = 0; ks < 2; ks++) {
            const uint32_t koff = (uint32_t)(ks * 32);
            uint32_t ahi[2][4], bf[4][4];

            uint32_t aA = sAhi + (uint32_t)((warpm * 32 + arow) * ROWB) + koff + akh * 16;
            LDSM4(ahi[0][0], ahi[0][1], ahi[0][2], ahi[0][3], aA);
            LDSM4(ahi[1][0], ahi[1][1], ahi[1][2], ahi[1][3], aA + 16 * ROWB);

            uint32_t aB = sB + (uint32_t)((warpn * 64 + brow) * ROWB) + koff + bkh * 16;
            #pragma unroll
            for (int jp = 0; jp < 4; jp++)
                LDSM4(bf[jp][0], bf[jp][1], bf[jp][2], bf[jp][3], aB + jp * 16 * ROWB);

            #pragma unroll
            for (int j = 0; j < 8; j++) {
                uint32_t b0 = bf[j >> 1][(j & 1) * 2];
                uint32_t b1 = bf[j >> 1][(j & 1) * 2 + 1];
                #pragma unroll
                for (int i = 0; i < 2; i++)
                    mma_f16(acc[i][j], ahi[i], b0, b1);
            }
        }
        __syncthreads();
    }

    float* stg = (float*)smem;
    #pragma unroll
    for (int i = 0; i < 2; i++) {
        int r = warpm * 32 + i * 16 + (lane >> 2);
        #pragma unroll
        for (int j = 0; j < 8; j++) {
            int c = warpn * 64 + j * 8 + (lane & 3) * 2;
            stg[r * 132 + c]           = acc[i][j][0];
            stg[r * 132 + c + 1]       = acc[i][j][1];
            stg[(r + 8) * 132 + c]     = acc[i][j][2];
            stg[(r + 8) * 132 + c + 1] = acc[i][j][3];
        }
    }
    __syncthreads();
    #pragma unroll
    for (int l = 0; l < 16; l++) {
        int f = tid + l * 256;
        int row = f >> 5, c4 = f & 31;
        *(float4*)&C[(size_t)(m0 + row) * D + n0 + c4 * 4] = *(float4*)&stg[row * 132 + c4 * 4];
    }
}

// ---------------- fused attention ----------------
__global__ __launch_bounds__(256, 5)
void k_fused(const float* __restrict__ bias1, float* __restrict__ Y) {
    __shared__ int cnt[400];
    __shared__ __align__(16) float Wm[NH][NPG][NPG];
    __shared__ __align__(16) float ssrc[NPG][NH];
    __shared__ __align__(16) float sdst[NPG][NH];
    __shared__ float dnm[NPG][NH];
    __shared__ __align__(16) float hsh[NPG][264];
    __shared__ __align__(16) float vsh[8][260];
    __shared__ float s2[NPG][8];
    __shared__ float mx2[NH], dnm2[NH];
    __shared__ float W19w[NH][NPG];

    const int g = blockIdx.x;
    const int tid = threadIdx.x;
    const int c = tid, h = c >> 6;
    const int base = g * NPG;

    float r[NPG];
    const float* hp = g_h1lin + (size_t)base * D;
    #pragma unroll
    for (int s = 0; s < NPG; s++) r[s] = hp[s * D + c];
    const float bv = bias1[c];

    for (int i = tid; i < 400; i += 256)
        cnt[i] = g_hist[g * 400 + i] + ((i % 21) == 0 ? 1 : 0);
    for (int i = tid; i < 2048; i += 256)
        vsh[i >> 8][i & 255] = g_v[i];
    if (tid < 160) {
        int i = tid >> 3, vec = tid & 7;
        float val = g_s1[(size_t)(base + i) * 8 + vec];
        if (vec < 4) ssrc[i][vec] = val; else sdst[i][vec - 4] = val;
    }
    __syncthreads();

    for (int e = tid; e < 400; e += 256) {
        int d = e / NPG, s = e - d * NPG;
        int ct = cnt[e];
        float wx = 0.f, wy = 0.f, wz = 0.f, ww = 0.f;
        if (ct) {
            float cf = (float)ct;
            float4 sv = *(const float4*)ssrc[s];
            float4 dv = *(const float4*)sdst[d];
            wx = cf * __expf(lrelu(sv.x + dv.x));
            wy = cf * __expf(lrelu(sv.y + dv.y));
            wz = cf * __expf(lrelu(sv.z + dv.z));
            ww = cf * __expf(lrelu(sv.w + dv.w));
        }
        Wm[0][d][s] = wx; Wm[1][d][s] = wy; Wm[2][d][s] = wz; Wm[3][d][s] = ww;
    }
    __syncthreads();
    if (tid < 80) {
        int d = tid >> 2, hh = tid & 3;
        float sum = 0.f;
        #pragma unroll
        for (int s = 0; s < NPG; s++) sum += Wm[hh][d][s];
        dnm[d][hh] = 1.f / (sum + 1e-16f);
    }
    __syncthreads();

    #pragma unroll
    for (int d = 0; d < NPG; d++) {
        const float4* wrow = (const float4*)Wm[h][d];
        float acc = 0.f;
        #pragma unroll
        for (int q = 0; q < 5; q++) {
            float4 wv = wrow[q];
            acc += wv.x * r[q * 4] + wv.y * r[q * 4 + 1] +
                   wv.z * r[q * 4 + 2] + wv.w * r[q * 4 + 3];
        }
        hsh[d][c] = eluf(acc * dnm[d][h] + bv);
    }
    __syncthreads();

    if (tid < 160) {
        int i = tid >> 3, vec = tid & 7;
        const float4* hr = (const float4*)hsh[i];
        const float4* vr = (const float4*)vsh[vec];
        float a0 = 0.f, a1 = 0.f, a2 = 0.f, a3 = 0.f;
        #pragma unroll
        for (int q = 0; q < 64; q += 4) {
            float4 x0 = hr[q],     y0 = vr[q];
            float4 x1 = hr[q + 1], y1 = vr[q + 1];
            float4 x2 = hr[q + 2], y2 = vr[q + 2];
            float4 x3 = hr[q + 3], y3 = vr[q + 3];
            a0 += x0.x * y0.x + x0.y * y0.y + x0.z * y0.z + x0.w * y0.w;
            a1 += x1.x * y1.x + x1.y * y1.y + x1.z * y1.z + x1.w * y1.w;
            a2 += x2.x * y2.x + x2.y * y2.y + x2.z * y2.z + x2.w * y2.w;
            a3 += x3.x * y3.x + x3.y * y3.y + x3.z * y3.z + x3.w * y3.w;
        }
        s2[i][vec] = (a0 + a1) + (a2 + a3);
    }
    __syncthreads();

    if (tid < NH) {
        float sd = s2[19][4 + tid];
        float m = -1e30f;
        #pragma unroll
        for (int s = 0; s < NPG; s++)
            if (cnt[380 + s]) m = fmaxf(m, lrelu(s2[s][tid] + sd));
        mx2[tid] = m;
    }
    __syncthreads();
    if (tid < 80) {
        int s = tid >> 2, hh = tid & 3;
        int ct = cnt[380 + s];
        W19w[hh][s] = ct ? (float)ct * __expf(lrelu(s2[s][hh] + s2[19][4 + hh]) - mx2[hh])
                         : 0.f;
    }
    __syncthreads();
    if (tid < NH) {
        float sum = 0.f;
        #pragma unroll
        for (int s = 0; s < NPG; s++) sum += W19w[tid][s];
        dnm2[tid] = 1.f / (sum + 1e-16f);
    }
    __syncthreads();

    float y[NH] = {0.f, 0.f, 0.f, 0.f};
    #pragma unroll
    for (int s = 0; s < NPG; s++) {
        float hv = hsh[s][c];
        #pragma unroll
        for (int hh = 0; hh < NH; hh++) y[hh] += W19w[hh][s] * hv;
    }
    float* yp = Y + (size_t)g * (NH * D) + c;
    #pragma unroll
    for (int hh = 0; hh < NH; hh++) yp[hh * D] = y[hh] * dnm2[hh];
}

// ---------------- tail: 8 graphs/block (R14-proven); resets hist ----------------
__global__ __launch_bounds__(256, 4)
void k_tail(const float* __restrict__ bias2, const float* __restrict__ bh,
            const float* __restrict__ Wc, const float* __restrict__ bc,
            float* __restrict__ out) {
    __shared__ float ysh[8][NH][D];
    __shared__ float xssh[8][D];
    __shared__ float b2sh[D];
    __shared__ float hidg[8][HIDC];
    __shared__ float wcsh[HIDC];

    const int tid = threadIdx.x;
    const int g0 = blockIdx.x * 8;
    const int c = tid, h = c >> 6;

    for (int i = tid; i < 8 * NH * D; i += 256)
        ((float*)ysh)[i] = g_Y[(size_t)g0 * (NH * D) + i];
    b2sh[c] = bias2[c];
    if (tid < HIDC) wcsh[tid] = Wc[tid];
    for (int i = tid; i < 8 * 400; i += 256) g_hist[g0 * 400 + i] = 0;
    __syncthreads();

    float acc[8] = {0.f, 0.f, 0.f, 0.f, 0.f, 0.f, 0.f, 0.f};
    #pragma unroll 4
    for (int k = 0; k < D; k++) {
        float wv = g_W2T[k * D + c];
        #pragma unroll
        for (int gg = 0; gg < 8; gg++) acc[gg] += ysh[gg][h][k] * wv;
    }
    #pragma unroll
    for (int gg = 0; gg < 8; gg++)
        xssh[gg][c] = eluf(acc[gg] + b2sh[c]);
    __syncthreads();

    {
        const int j = tid & 63, gp = tid >> 6;
        float a0 = 0.f, a1 = 0.f;
        #pragma unroll 4
        for (int k = 0; k < D; k++) {
            float wv = g_WhT[k * HIDC + j];
            a0 += xssh[gp][k] * wv;
            a1 += xssh[gp + 4][k] * wv;
        }
        float bj = bh[j];
        float v0 = a0 + bj, v1 = a1 + bj;
        hidg[gp][j]     = (v0 > 0.f) ? v0 : 0.f;
        hidg[gp + 4][j] = (v1 > 0.f) ? v1 : 0.f;
    }
    __syncthreads();

    {
        const int lane = tid & 31, ww = tid >> 5;
        float s = hidg[ww][lane] * wcsh[lane] + hidg[ww][lane + 32] * wcsh[lane + 32];
        #pragma unroll
        for (int o = 16; o; o >>= 1) s += __shfl_xor_sync(0xffffffffu, s, o);
        if (lane == 0) out[g0 + ww] = s + bc[0];
    }
}

// ---------------- launcher ----------------
extern "C" void kernel_launch(void* const* d_in, const int* in_sizes, int n_in,
                              void* d_out, int out_size) {
    const float* x   = (const float*)d_in[0];
    const int*   ei  = (const int*)d_in[1];
    const float* W1  = (const float*)d_in[3];
    const float* a1s = (const float*)d_in[4];
    const float* a1d = (const float*)d_in[5];
    const float* b1  = (const float*)d_in[6];
    const float* W2  = (const float*)d_in[7];
    const float* a2s = (const float*)d_in[8];
    const float* a2d = (const float*)d_in[9];
    const float* b2  = (const float*)d_in[10];
    const float* Wh  = (const float*)d_in[11];
    const float* bh  = (const float*)d_in[12];
    const float* Wc  = (const float*)d_in[13];
    const float* bc  = (const float*)d_in[14];
    float* out = (float*)d_out;

    void *p_h1lin, *p_xhi, *p_w1h, *p_Y;
    cudaGetSymbolAddress(&p_h1lin, g_h1lin);
    cudaGetSymbolAddress(&p_xhi, g_xhi);
    cudaGetSymbolAddress(&p_w1h, g_w1h);
    cudaGetSymbolAddress(&p_Y, g_Y);

    cudaFuncSetAttribute(k_gemm_mma<IND>, cudaFuncAttributeMaxDynamicSharedMemorySize, GEMM_SMEM);

    k_hist<<<(NEDGES + 255) / 256, 256>>>(ei);                                          // idx0
    k_prep<<<(PREP_TOTAL + 255) / 256, 256>>>(x, W1, W2, a1s, a1d, a2s, a2d, Wh);       // idx1
    k_score<<<NNODES / 32, 256>>>(x);                                                   // idx2
    k_gemm_mma<IND><<<dim3(NNODES / 128, 2), 256, GEMM_SMEM>>>(                         // idx3
        (const __half*)p_xhi, (const __half*)p_w1h, (float*)p_h1lin);
    k_fused<<<NG, 256>>>(b1, (float*)p_Y);                                              // idx4
    k_tail<<<NG / 8, 256>>>(b2, bh, Wc, bc, out);                                       // idx5
}